// round 15
// baseline (speedup 1.0000x reference)
#include <cuda_runtime.h>
#include <cuda_fp16.h>
#include <cstdint>

#define BN    32
#define CH    256
#define HH    56
#define WW    56
#define HW    (HH*WW)            // 3136
#define TOTAL (BN*CH*HW)         // 25690112
#define WELEMS (CH*CH*9)         // 589824
#define NTILES (49*BN)           // 1568 (7x7 tiles per image)

// -------- device scratch ----------------------------------------------------
__device__ __half        g_a16[TOTAL];             // raw conv acc (exact ints)
__device__ unsigned char g_fx[(size_t)BN*HW*CH];   // sign(x) e4m3, channel-last
__device__ unsigned char g_wf8[9*CH*CH];           // sign(w) e4m3 [tap][n][ci]
__device__ float         g_msum;
__device__ float         g_meanval;
__device__ unsigned      g_tile;
__device__ float         g_csum[CH];
__device__ float         g_csq[CH];
__device__ float         g_scale[CH];
__device__ float         g_bias[CH];

__device__ __forceinline__ unsigned char sgn_e4m3(float v) {
    return v > 0.f ? 0x38u : (v < 0.f ? 0xB8u : 0x00u);
}

// ---------------- P-1: zero accumulators + tile counter --------------------
__global__ void k_init() {
    if (threadIdx.x == 0) { g_msum = 0.f; g_tile = 0u; }
    g_csum[threadIdx.x] = 0.f;
    g_csq[threadIdx.x] = 0.f;
}

// ---------------- P0: mean(|clip(w,-1,1)|) partials, 36 blocks -------------
__global__ void k_meanval(const float* __restrict__ w) {
    __shared__ float red[256];
    const float4* wv = (const float4*)w;
    float s = 0.f;
#pragma unroll
    for (int i = 0; i < 16; i++) {
        float4 v = wv[blockIdx.x * 4096 + i * 256 + threadIdx.x];
        float a0 = fabsf(v.x), a1 = fabsf(v.y), a2 = fabsf(v.z), a3 = fabsf(v.w);
        s += ((a0 < 1.f) ? a0 : 1.f) + ((a1 < 1.f) ? a1 : 1.f)
           + ((a2 < 1.f) ? a2 : 1.f) + ((a3 < 1.f) ? a3 : 1.f);
    }
    red[threadIdx.x] = s;
    __syncthreads();
    for (int o = 128; o > 0; o >>= 1) {
        if (threadIdx.x < o) red[threadIdx.x] += red[threadIdx.x + o];
        __syncthreads();
    }
    if (threadIdx.x == 0) atomicAdd(&g_msum, red[0]);
}

// ---------------- P1: sign(w) -> e4m3 [tap][n][ci]; finalize meanval -------
__global__ void k_packw(const float* __restrict__ w) {
    if (blockIdx.x == 0 && threadIdx.x == 0)
        g_meanval = g_msum / (float)WELEMS;
    int idx = blockIdx.x * 256 + threadIdx.x;
    if (idx >= 9 * CH * CH) return;
    int ci  = idx & 255;
    int n   = (idx >> 8) & 255;
    int tap = idx >> 16;
    g_wf8[idx] = sgn_e4m3(w[(n * CH + ci) * 9 + tap]);
}

// ---------------- P2: sign(x) -> channel-last e4m3 bytes -------------------
#define XP 260
__global__ void k_packx(const float* __restrict__ x) {
    __shared__ unsigned char tile[WW * XP];
    int b = blockIdx.x / HH, h = blockIdx.x % HH;
    for (int i = threadIdx.x; i < CH * WW; i += 256) {
        int c = i / WW, w = i - c * WW;
        tile[w * XP + c] = sgn_e4m3(x[((b * CH + c) * HH + h) * WW + w]);
    }
    __syncthreads();
    unsigned* dst = (unsigned*)g_fx;
    for (int j = threadIdx.x; j < WW * 64; j += 256) {
        int w = j >> 6, q = j & 63;
        unsigned v = *(const unsigned*)&tile[w * XP + q * 4];
        dst[((size_t)(b * HH + h) * WW + w) * 64 + q] = v;
    }
}

// ---------------- conv helpers ---------------------------------------------
__device__ __forceinline__ void mmaf8(float* c, const unsigned* a, const unsigned* b) {
    asm volatile(
        "mma.sync.aligned.m16n8k32.row.col.f32.e4m3.e4m3.f32 "
        "{%0,%1,%2,%3}, {%4,%5,%6,%7}, {%8,%9}, {%0,%1,%2,%3};\n"
        : "+f"(c[0]), "+f"(c[1]), "+f"(c[2]), "+f"(c[3])
        : "r"(a[0]), "r"(a[1]), "r"(a[2]), "r"(a[3]), "r"(b[0]), "r"(b[1]));
}
__device__ __forceinline__ void ldmx4(unsigned* r, uint32_t saddr) {
    asm volatile("ldmatrix.sync.aligned.m8n8.x4.shared.b16 {%0,%1,%2,%3}, [%4];"
        : "=r"(r[0]), "=r"(r[1]), "=r"(r[2]), "=r"(r[3]) : "r"(saddr));
}
#define CP16(dst, src) asm volatile("cp.async.cg.shared.global [%0], [%1], 16;" :: "r"(dst), "l"(src))
#define CP_COMMIT()    asm volatile("cp.async.commit_group;")
#define CP_WAIT0()     asm volatile("cp.async.wait_group 0;")

#define APITCH 272                        // A row: 256B data + 16B pad
#define ABYTES (100 * APITCH)             // 27200 (10x10 halo)
#define BPITCH 144                        // B row: 128B (one ci-half) + 16B pad
#define BBUF   (256 * BPITCH)             // 36864 per buffer
#define CONV_SMEM (ABYTES + 2 * BBUF)     // 100928 -> 2 CTAs/SM

// Persistent CTAs: 296 blocks, work-steal 1568 tiles.
// Tile: 64 px (8h x 8w) x 256 cout; 16 warps = 2(m) x 8(n); warp 32px x 32co
__global__ __launch_bounds__(512, 2) void k_conv(const float* __restrict__ x) {
    extern __shared__ unsigned char smem[];
    __shared__ int s_tile;
    const uint32_t sA = (uint32_t)__cvta_generic_to_shared(smem);
    const uint32_t sB[2] = { sA + ABYTES, sA + ABYTES + BBUF };

    const int tid = threadIdx.x;
    const int warp = tid >> 5, lane = tid & 31;
    const int grp = lane >> 2, tig = lane & 3;
    const int wm = warp >> 3, wn = warp & 7;

    // lane-address components (tile-invariant)
    const int lrow8 = (lane >> 3) & 1;
    const int lcol  = lane & 7;
    const int lhalf = (lane >> 4) * 16;
    const int pmrow = wm * 4;
    const int bm = lane >> 3, bi = lane & 7;
    const int bkh = (bm & 1) * 16;
    uint32_t bbase[2][2];
#pragma unroll
    for (int bufi = 0; bufi < 2; bufi++)
#pragma unroll
        for (int bh = 0; bh < 2; bh++)
            bbase[bufi][bh] = sB[bufi] +
                (uint32_t)((wn * 32 + (bh * 2 + (bm >> 1)) * 8 + bi) * BPITCH) + bkh;
    const float mv = g_meanval;

    for (;;) {
        if (tid == 0) s_tile = (int)atomicAdd(&g_tile, 1u);
        __syncthreads();
        const int t = s_tile;
        if (t >= NTILES) break;
        const int b = t / 49, rr = t % 49;
        const int th = rr / 7, tw = rr % 7;
        const int h0 = th * 8, w0 = tw * 8;

        // ---- stage A: 256-ch halo, 100 px (10h x 10w), zero-padded borders
        for (int j = tid; j < 100 * 16; j += 512) {       // uint4 units
            int p = j >> 4, q = j & 15;
            int nh = h0 - 1 + p / 10;
            int nw = w0 - 1 + p % 10;
            uint4 v = make_uint4(0u, 0u, 0u, 0u);
            if (nh >= 0 && nh < HH && nw >= 0 && nw < WW)
                v = *(const uint4*)(g_fx + ((size_t)((b * HH + nh) * WW + nw)) * CH + q * 16);
            *(uint4*)(smem + p * APITCH + q * 16) = v;
        }
        // ---- stage B for it 0 (tap 0, ci-half 0) via cp.async
        {
            const char* wsrc = (const char*)g_wf8;
            for (int j = tid; j < 2048; j += 512) {
                int r = j >> 3, q = j & 7;
                CP16(sB[0] + (uint32_t)(r * BPITCH + q * 16), wsrc + r * 256 + q * 16);
            }
            CP_COMMIT();
            CP_WAIT0();
        }
        __syncthreads();

        float acc[2][4][4];
#pragma unroll
        for (int i = 0; i < 2; i++)
#pragma unroll
            for (int j = 0; j < 4; j++)
#pragma unroll
                for (int e = 0; e < 4; e++) acc[i][j][e] = 0.f;

        for (int it = 0; it < 18; it++) {                 // 9 taps x 2 ci-halves
            const int tap = it >> 1, half = it & 1;
            const int dh = tap / 3, dw = tap % 3;

            if (it + 1 < 18) {
                const int ntap = (it + 1) >> 1, nhalf = (it + 1) & 1;
                const char* wsrc = (const char*)(g_wf8 + ntap * 65536 + nhalf * 128);
                const uint32_t dstb = sB[(it + 1) & 1];
                for (int j = tid; j < 2048; j += 512) {
                    int r = j >> 3, q = j & 7;
                    CP16(dstb + (uint32_t)(r * BPITCH + q * 16), wsrc + r * 256 + q * 16);
                }
                CP_COMMIT();
            }
            const int bufi = it & 1;

            uint32_t abase[2];
#pragma unroll
            for (int fm = 0; fm < 2; fm++) {
                int nbrow = (pmrow + fm * 2 + lrow8 + dh) * 10 + lcol + dw;
                abase[fm] = sA + (uint32_t)(nbrow * APITCH + half * 128) + lhalf;
            }

#pragma unroll
            for (int ks = 0; ks < 4; ks++) {              // 4 x k32 covers 128 ci
                unsigned afr[2][4];
#pragma unroll
                for (int fm = 0; fm < 2; fm++)
                    ldmx4(afr[fm], abase[fm] + ks * 32);
                unsigned bfr[2][4];
                ldmx4(bfr[0], bbase[bufi][0] + ks * 32);
                ldmx4(bfr[1], bbase[bufi][1] + ks * 32);
#pragma unroll
                for (int fm = 0; fm < 2; fm++)
#pragma unroll
                    for (int fn = 0; fn < 4; fn++)
                        mmaf8(acc[fm][fn], afr[fm], &bfr[fn >> 1][(fn & 1) * 2]);
            }
            CP_WAIT0();
            __syncthreads();
        }

        // ---- epilogue: store fp16 acc (exact); fused per-channel BN partials
#pragma unroll
        for (int fn = 0; fn < 4; fn++) {
#pragma unroll
            for (int e1 = 0; e1 < 2; e1++) {
                const int co = wn * 32 + fn * 8 + tig * 2 + e1;
                float s = 0.f, q = 0.f;
#pragma unroll
                for (int fm = 0; fm < 2; fm++) {
#pragma unroll
                    for (int e2 = 0; e2 < 2; e2++) {
                        int p = wm * 32 + fm * 16 + grp + e2 * 8;
                        int h = h0 + (p >> 3), w = w0 + (p & 7);
                        int idx = ((b * CH + co) * HH + h) * WW + w;
                        float a = acc[fm][fn][e2 * 2 + e1];
                        g_a16[idx] = __float2half_rn(a);
                        float v = mv * a + x[idx];
                        s += v;
                        q += v * v;
                    }
                }
                s += __shfl_xor_sync(0xFFFFFFFFu, s, 4);
                q += __shfl_xor_sync(0xFFFFFFFFu, q, 4);
                s += __shfl_xor_sync(0xFFFFFFFFu, s, 8);
                q += __shfl_xor_sync(0xFFFFFFFFu, q, 8);
                s += __shfl_xor_sync(0xFFFFFFFFu, s, 16);
                q += __shfl_xor_sync(0xFFFFFFFFu, q, 16);
                if (grp == 0) {
                    atomicAdd(&g_csum[co], s);
                    atomicAdd(&g_csq[co], q);
                }
            }
        }
        __syncthreads();   // epilogue done before next tile restages smem
    }
}

// ---------------- R: finalize BN scale/bias --------------------------------
__global__ void k_bnfin(const float* __restrict__ gamma, const float* __restrict__ beta) {
    int c = threadIdx.x;
    const float inv = 1.f / (float)(BN * HW);
    float mean = g_csum[c] * inv;
    float var  = g_csq[c] * inv - mean * mean;
    float sc = gamma[c] * rsqrtf(var + 1e-5f);
    g_scale[c] = sc;
    g_bias[c]  = beta[c] - mean * sc;
}

// ---------------- E: v = mv*acc + x; out = relu(sc*v + bi) -----------------
__global__ void k_finish(const float* __restrict__ x, float4* __restrict__ out) {
    int i = blockIdx.x * 256 + threadIdx.x;
    int c = (i / (HW / 4)) % CH;
    float sc = g_scale[c], bi = g_bias[c], mv = g_meanval;
    float4 xv = ((const float4*)x)[i];
    __half2 h01 = ((const __half2*)g_a16)[i * 2];
    __half2 h23 = ((const __half2*)g_a16)[i * 2 + 1];
    float a0 = __half2float(__low2half(h01)), a1 = __half2float(__high2half(h01));
    float a2 = __half2float(__low2half(h23)), a3 = __half2float(__high2half(h23));
    float4 r;
    r.x = fmaxf(sc * (mv * a0 + xv.x) + bi, 0.f);
    r.y = fmaxf(sc * (mv * a1 + xv.y) + bi, 0.f);
    r.z = fmaxf(sc * (mv * a2 + xv.z) + bi, 0.f);
    r.w = fmaxf(sc * (mv * a3 + xv.w) + bi, 0.f);
    out[i] = r;
}

// ---------------- launch ---------------------------------------------------
extern "C" void kernel_launch(void* const* d_in, const int* in_sizes, int n_in,
                              void* d_out, int out_size) {
    const float* x     = (const float*)d_in[0];
    const float* w     = (const float*)d_in[1];
    const float* gamma = (const float*)d_in[2];
    const float* beta  = (const float*)d_in[3];

    cudaFuncSetAttribute(k_conv, cudaFuncAttributeMaxDynamicSharedMemorySize, CONV_SMEM);

    k_init<<<1, 256>>>();
    k_meanval<<<36, 256>>>(w);
    k_packw<<<(9 * CH * CH + 255) / 256, 256>>>(w);
    k_packx<<<BN * HH, 256>>>(x);
    k_conv<<<296, 512, CONV_SMEM>>>(x);
    k_bnfin<<<1, CH>>>(gamma, beta);
    k_finish<<<TOTAL / 4 / 256, 256>>>(x, (float4*)d_out);
}

// round 16
// speedup vs baseline: 1.0301x; 1.0301x over previous
#include <cuda_runtime.h>
#include <cstdint>

#define BN    32
#define CH    256
#define HH    56
#define WW    56
#define HW    (HH*WW)            // 3136
#define TOTAL (BN*CH*HW)         // 25690112
#define WELEMS (CH*CH*9)         // 589824

// -------- device scratch ----------------------------------------------------
__device__ float         g_pre[TOTAL];             // conv + residual (pre-BN)
__device__ unsigned char g_fx[(size_t)BN*HW*CH];   // sign(x) e4m3, channel-last
__device__ unsigned char g_wf8[9*CH*CH];           // sign(w) e4m3 [tap][n][ci]
__device__ float         g_msum;
__device__ float         g_csum[CH];
__device__ float         g_csq[CH];
__device__ float         g_scale[CH];
__device__ float         g_bias[CH];

__device__ __forceinline__ unsigned char sgn_e4m3(float v) {
    return v > 0.f ? 0x38u : (v < 0.f ? 0xB8u : 0x00u);
}

// ---------------- P-1: zero accumulators -----------------------------------
__global__ void k_init() {
    if (threadIdx.x == 0) g_msum = 0.f;
    g_csum[threadIdx.x] = 0.f;
    g_csq[threadIdx.x] = 0.f;
}

// ---------------- P1: sign(w) -> e4m3 [tap][n][ci] + fused mean partials ---
__global__ void k_packw(const float* __restrict__ w) {
    __shared__ float red[256];
    int idx = blockIdx.x * 256 + threadIdx.x;
    float a = 0.f;
    if (idx < 9 * CH * CH) {
        int ci  = idx & 255;
        int n   = (idx >> 8) & 255;
        int tap = idx >> 16;
        float wv = w[(n * CH + ci) * 9 + tap];
        g_wf8[idx] = sgn_e4m3(wv);
        a = fabsf(wv);
        a = (a < 1.f) ? a : 1.f;
    }
    red[threadIdx.x] = a;
    __syncthreads();
    for (int o = 128; o > 0; o >>= 1) {
        if (threadIdx.x < o) red[threadIdx.x] += red[threadIdx.x + o];
        __syncthreads();
    }
    if (threadIdx.x == 0) atomicAdd(&g_msum, red[0]);
}

// ---------------- P2: sign(x) -> channel-last e4m3 bytes (vectorized) ------
#define XP 260
__global__ void k_packx(const float* __restrict__ x) {
    __shared__ unsigned char tile[WW * XP];
    int b = blockIdx.x / HH, h = blockIdx.x % HH;
    const float* xb = x + (size_t)b * CH * HW + h * WW;
    // each iteration: one u32 = 4 channels at one w
    for (int i = threadIdx.x; i < 64 * WW; i += 256) {
        int c4 = i / WW, w = i - c4 * WW;
        const float* xc = xb + (size_t)(c4 * 4) * HW + w;
        unsigned v = (unsigned)sgn_e4m3(xc[0])
                   | ((unsigned)sgn_e4m3(xc[HW])     << 8)
                   | ((unsigned)sgn_e4m3(xc[2 * HW]) << 16)
                   | ((unsigned)sgn_e4m3(xc[3 * HW]) << 24);
        *(unsigned*)&tile[w * XP + c4 * 4] = v;
    }
    __syncthreads();
    unsigned* dst = (unsigned*)g_fx;
    for (int j = threadIdx.x; j < WW * 64; j += 256) {
        int w = j >> 6, q = j & 63;
        unsigned v = *(const unsigned*)&tile[w * XP + q * 4];
        dst[((size_t)(b * HH + h) * WW + w) * 64 + q] = v;
    }
}

// ---------------- conv helpers ---------------------------------------------
__device__ __forceinline__ void mmaf8(float* c, const unsigned* a, const unsigned* b) {
    asm volatile(
        "mma.sync.aligned.m16n8k32.row.col.f32.e4m3.e4m3.f32 "
        "{%0,%1,%2,%3}, {%4,%5,%6,%7}, {%8,%9}, {%0,%1,%2,%3};\n"
        : "+f"(c[0]), "+f"(c[1]), "+f"(c[2]), "+f"(c[3])
        : "r"(a[0]), "r"(a[1]), "r"(a[2]), "r"(a[3]), "r"(b[0]), "r"(b[1]));
}
__device__ __forceinline__ void ldmx4(unsigned* r, uint32_t saddr) {
    asm volatile("ldmatrix.sync.aligned.m8n8.x4.shared.b16 {%0,%1,%2,%3}, [%4];"
        : "=r"(r[0]), "=r"(r[1]), "=r"(r[2]), "=r"(r[3]) : "r"(saddr));
}
#define CP16(dst, src) asm volatile("cp.async.cg.shared.global [%0], [%1], 16;" :: "r"(dst), "l"(src))
#define CP_COMMIT()    asm volatile("cp.async.commit_group;")
#define CP_WAIT0()     asm volatile("cp.async.wait_group 0;")

#define APITCH 272                        // A row: 256B data + 16B pad
#define ABYTES (100 * APITCH)             // 27200 (10x10 halo)
#define BPITCH 144                        // B row: 128B (one ci-half) + 16B pad
#define BBUF   (256 * BPITCH)             // 36864 per buffer
#define CONV_SMEM (ABYTES + 2 * BBUF)     // 100928 -> 2 CTAs/SM

// CTA: 64 px (8h x 8w) x 256 cout; 16 warps = 2(m) x 8(n); warp 32px x 32co
__global__ __launch_bounds__(512, 2) void k_conv(const float* __restrict__ x) {
    extern __shared__ unsigned char smem[];
    const uint32_t sA = (uint32_t)__cvta_generic_to_shared(smem);
    const uint32_t sB[2] = { sA + ABYTES, sA + ABYTES + BBUF };

    const int tid = threadIdx.x;
    const int warp = tid >> 5, lane = tid & 31;
    const int grp = lane >> 2, tig = lane & 3;
    const int wm = warp >> 3, wn = warp & 7;
    const int tw = blockIdx.x, th = blockIdx.y, b = blockIdx.z;
    const int h0 = th * 8, w0 = tw * 8;

    // ---- stage A: 256-ch halo, 100 px (10h x 10w), zero-padded borders
    {
        for (int j = tid; j < 100 * 16; j += 512) {       // uint4 units
            int p = j >> 4, q = j & 15;
            int nh = h0 - 1 + p / 10;
            int nw = w0 - 1 + p % 10;
            uint4 v = make_uint4(0u, 0u, 0u, 0u);
            if (nh >= 0 && nh < HH && nw >= 0 && nw < WW)
                v = *(const uint4*)(g_fx + ((size_t)((b * HH + nh) * WW + nw)) * CH + q * 16);
            *(uint4*)(smem + p * APITCH + q * 16) = v;
        }
    }
    // ---- stage B for it 0 (tap 0, ci-half 0) via cp.async
    {
        const char* wsrc = (const char*)g_wf8;
        for (int j = tid; j < 2048; j += 512) {           // uint4 units
            int r = j >> 3, q = j & 7;
            CP16(sB[0] + (uint32_t)(r * BPITCH + q * 16), wsrc + r * 256 + q * 16);
        }
        CP_COMMIT();
        CP_WAIT0();
    }
    __syncthreads();

    float acc[2][4][4];
#pragma unroll
    for (int i = 0; i < 2; i++)
#pragma unroll
        for (int j = 0; j < 4; j++)
#pragma unroll
            for (int e = 0; e < 4; e++) acc[i][j][e] = 0.f;

    // ldmatrix lane-address components
    const int lrow8 = (lane >> 3) & 1;    // A: +8 px (one h-row) for matrices 1,3
    const int lcol  = lane & 7;           // A: px col within 8
    const int lhalf = (lane >> 4) * 16;   // A: +16B (k bytes 16..31)
    const int pmrow = wm * 4;             // warp m-tile = 32 px = 4 h-rows

    // B lane bases: m = lane>>3; n-group = bh*2 + (m>>1); khalf = m&1
    const int bm = lane >> 3, bi = lane & 7;
    const int bkh = (bm & 1) * 16;
    uint32_t bbase[2][2];
#pragma unroll
    for (int bufi = 0; bufi < 2; bufi++)
#pragma unroll
        for (int bh = 0; bh < 2; bh++)
            bbase[bufi][bh] = sB[bufi] +
                (uint32_t)((wn * 32 + (bh * 2 + (bm >> 1)) * 8 + bi) * BPITCH) + bkh;

    for (int it = 0; it < 18; it++) {                     // 9 taps x 2 ci-halves
        const int tap = it >> 1, half = it & 1;
        const int dh = tap / 3, dw = tap % 3;

        // prefetch next iteration's B into the other buffer
        if (it + 1 < 18) {
            const int ntap = (it + 1) >> 1, nhalf = (it + 1) & 1;
            const char* wsrc = (const char*)(g_wf8 + ntap * 65536 + nhalf * 128);
            const uint32_t dstb = sB[(it + 1) & 1];
            for (int j = tid; j < 2048; j += 512) {
                int r = j >> 3, q = j & 7;
                CP16(dstb + (uint32_t)(r * BPITCH + q * 16), wsrc + r * 256 + q * 16);
            }
            CP_COMMIT();
        }
        const int bufi = it & 1;

        // per-fm A base addresses for this tap / ci-half
        uint32_t abase[2];
#pragma unroll
        for (int fm = 0; fm < 2; fm++) {
            int nbrow = (pmrow + fm * 2 + lrow8 + dh) * 10 + lcol + dw;
            abase[fm] = sA + (uint32_t)(nbrow * APITCH + half * 128) + lhalf;
        }

#pragma unroll
        for (int ks = 0; ks < 4; ks++) {              // 4 x k32 covers 128 ci
            unsigned afr[2][4];
#pragma unroll
            for (int fm = 0; fm < 2; fm++)
                ldmx4(afr[fm], abase[fm] + ks * 32);
            unsigned bfr[2][4];
            ldmx4(bfr[0], bbase[bufi][0] + ks * 32);
            ldmx4(bfr[1], bbase[bufi][1] + ks * 32);
#pragma unroll
            for (int fm = 0; fm < 2; fm++)
#pragma unroll
                for (int fn = 0; fn < 4; fn++)
                    mmaf8(acc[fm][fn], afr[fm], &bfr[fn >> 1][(fn & 1) * 2]);
        }
        CP_WAIT0();
        __syncthreads();
    }

    // ---- epilogue: v = mv*acc + x -> g_pre; fused per-channel BN partials
    const float mv = g_msum * (1.f / (float)WELEMS);
#pragma unroll
    for (int fn = 0; fn < 4; fn++) {
#pragma unroll
        for (int e1 = 0; e1 < 2; e1++) {
            const int co = wn * 32 + fn * 8 + tig * 2 + e1;
            float s = 0.f, q = 0.f;
#pragma unroll
            for (int fm = 0; fm < 2; fm++) {
#pragma unroll
                for (int e2 = 0; e2 < 2; e2++) {
                    int p = wm * 32 + fm * 16 + grp + e2 * 8;
                    int h = h0 + (p >> 3), w = w0 + (p & 7);
                    int idx = ((b * CH + co) * HH + h) * WW + w;
                    float v = mv * acc[fm][fn][e2 * 2 + e1] + x[idx];
                    g_pre[idx] = v;
                    s += v;
                    q += v * v;
                }
            }
            s += __shfl_xor_sync(0xFFFFFFFFu, s, 4);
            q += __shfl_xor_sync(0xFFFFFFFFu, q, 4);
            s += __shfl_xor_sync(0xFFFFFFFFu, s, 8);
            q += __shfl_xor_sync(0xFFFFFFFFu, q, 8);
            s += __shfl_xor_sync(0xFFFFFFFFu, s, 16);
            q += __shfl_xor_sync(0xFFFFFFFFu, q, 16);
            if (grp == 0) {
                atomicAdd(&g_csum[co], s);
                atomicAdd(&g_csq[co], q);
            }
        }
    }
}

// ---------------- R: finalize BN scale/bias --------------------------------
__global__ void k_bnfin(const float* __restrict__ gamma, const float* __restrict__ beta) {
    int c = threadIdx.x;
    const float inv = 1.f / (float)(BN * HW);
    float mean = g_csum[c] * inv;
    float var  = g_csq[c] * inv - mean * mean;
    float sc = gamma[c] * rsqrtf(var + 1e-5f);
    g_scale[c] = sc;
    g_bias[c]  = beta[c] - mean * sc;
}

// ---------------- E: apply BN affine + ReLU --------------------------------
__global__ void k_finish(float4* __restrict__ out) {
    int i = blockIdx.x * 256 + threadIdx.x;
    int c = (i / (HW / 4)) % CH;
    float sc = g_scale[c], bi = g_bias[c];
    float4 v = ((const float4*)g_pre)[i];
    float4 r;
    r.x = fmaxf(v.x * sc + bi, 0.f);
    r.y = fmaxf(v.y * sc + bi, 0.f);
    r.z = fmaxf(v.z * sc + bi, 0.f);
    r.w = fmaxf(v.w * sc + bi, 0.f);
    out[i] = r;
}

// ---------------- launch ---------------------------------------------------
extern "C" void kernel_launch(void* const* d_in, const int* in_sizes, int n_in,
                              void* d_out, int out_size) {
    const float* x     = (const float*)d_in[0];
    const float* w     = (const float*)d_in[1];
    const float* gamma = (const float*)d_in[2];
    const float* beta  = (const float*)d_in[3];

    cudaFuncSetAttribute(k_conv, cudaFuncAttributeMaxDynamicSharedMemorySize, CONV_SMEM);

    k_init<<<1, 256>>>();
    k_packw<<<(9 * CH * CH + 255) / 256, 256>>>(w);
    k_packx<<<BN * HH, 256>>>(x);
    k_conv<<<dim3(7, 7, BN), 512, CONV_SMEM>>>(x);
    k_bnfin<<<1, CH>>>(gamma, beta);
    k_finish<<<TOTAL / 4 / 256, 256>>>((float4*)d_out);
}